// round 1
// baseline (speedup 1.0000x reference)
#include <cuda_runtime.h>
#include <cuda_fp16.h>

#define NPTS (1 << 19)
#define NG 64
#define NVOX (64 * 64 * 64)

// Static device scratch (allocation-free per harness rules)
__device__ float4 g_xf[NG * 3];          // fused (rot*scale*31.5 | bias) rows
__device__ float2 g_w2[32];              // W2 as float2 pairs
__device__ uint4  g_feat[NG * NVOX];     // 256 MB: per-voxel 2x2 corner-duplicated fp16 (2ch)

static __device__ __forceinline__ unsigned long long ffma2(
    unsigned long long a, unsigned long long b, unsigned long long c) {
  unsigned long long d;
  asm("fma.rn.f32x2 %0, %1, %2, %3;" : "=l"(d) : "l"(a), "l"(b), "l"(c));
  return d;
}
static __device__ __forceinline__ unsigned long long pack2(float a, float b) {
  unsigned long long r;
  asm("mov.b64 %0, {%1, %2};" : "=l"(r) : "f"(a), "f"(b));
  return r;
}
static __device__ __forceinline__ float2 unpack2(unsigned long long v) {
  float2 r;
  asm("mov.b64 {%0, %1}, %2;" : "=f"(r.x), "=f"(r.y) : "l"(v));
  return r;
}
static __device__ __forceinline__ unsigned pack_h2(float a, float b) {
  __half2 h = __floats2half2_rn(a, b);
  return *reinterpret_cast<unsigned*>(&h);
}

// ---------------------------------------------------------------------------
// Kernel 0: fold quaternion->rotation, scale, translate, and grid-coord affine
// into one 3x4 matrix per grid:  gcoord = A * p + b,  A = 31.5*s_i*R_ij,
// b = 31.5*t_i + 31.5.  Also stage W2.
// ---------------------------------------------------------------------------
__global__ void k_prep(const float* __restrict__ r, const float* __restrict__ s,
                       const float* __restrict__ t, const float* __restrict__ w2) {
  int g = threadIdx.x;
  if (g >= NG) return;
  float qw = r[g * 4 + 0], qx = r[g * 4 + 1], qy = r[g * 4 + 2], qz = r[g * 4 + 3];
  float inv = 1.0f / sqrtf(qw * qw + qx * qx + qy * qy + qz * qz);
  qw *= inv; qx *= inv; qy *= inv; qz *= inv;
  float R[9];
  R[0] = 1.f - 2.f * (qy * qy + qz * qz); R[1] = 2.f * (qx * qy - qw * qz); R[2] = 2.f * (qx * qz + qw * qy);
  R[3] = 2.f * (qx * qy + qw * qz); R[4] = 1.f - 2.f * (qx * qx + qz * qz); R[5] = 2.f * (qy * qz - qw * qx);
  R[6] = 2.f * (qx * qz - qw * qy); R[7] = 2.f * (qy * qz + qw * qx); R[8] = 1.f - 2.f * (qx * qx + qy * qy);
#pragma unroll
  for (int i = 0; i < 3; i++) {
    float si = 31.5f * s[g * 3 + i];
    g_xf[g * 3 + i] = make_float4(si * R[i * 3 + 0], si * R[i * 3 + 1], si * R[i * 3 + 2],
                                  31.5f * t[g * 3 + i] + 31.5f);
  }
  reinterpret_cast<float*>(g_w2)[g] = w2[g];
}

// ---------------------------------------------------------------------------
// Kernel 1: repack features [G,2,64,64,64] fp32 -> corner-duplicated fp16.
// Entry (g,z,y,x) = uint4 of 4 half2:
//   .x = (c0,c1)(y  ,x  )   .y = (c0,c1)(y  ,min(x+1,63))
//   .z = (c0,c1)(min(y+1,63),x)   .w = (c0,c1)(min(y+1,63),min(x+1,63))
// One block per (g,z) slice; slice staged in shared so global reads happen once.
// ---------------------------------------------------------------------------
__global__ void k_repack(const float* __restrict__ feat) {
  __shared__ float s0[4096];
  __shared__ float s1[4096];
  int b = blockIdx.x;            // b = g*64 + z
  int g = b >> 6;
  const float* p0 = feat + (((size_t)(2 * g)) << 18) + (((size_t)(b & 63)) << 12);
  const float* p1 = feat + (((size_t)(2 * g + 1)) << 18) + (((size_t)(b & 63)) << 12);
  for (int i = threadIdx.x; i < 4096; i += 256) { s0[i] = p0[i]; s1[i] = p1[i]; }
  __syncthreads();
  uint4* op = g_feat + (((size_t)b) << 12);
  for (int i = threadIdx.x; i < 4096; i += 256) {
    int y = i >> 6, xx = i & 63;
    int x1 = min(xx + 1, 63), y1 = min(y + 1, 63);
    uint4 e;
    e.x = pack_h2(s0[(y << 6) | xx], s1[(y << 6) | xx]);
    e.y = pack_h2(s0[(y << 6) | x1], s1[(y << 6) | x1]);
    e.z = pack_h2(s0[(y1 << 6) | xx], s1[(y1 << 6) | xx]);
    e.w = pack_h2(s0[(y1 << 6) | x1], s1[(y1 << 6) | x1]);
    op[i] = e;
  }
}

// ---------------------------------------------------------------------------
// Kernel 2: fused sample + MLP.  One thread per point (grid-stride).
// h0 accumulated grid-by-grid as 32 packed f32x2 pairs; W0^T / W1^T staged
// transposed in shared so every k-row is 16B-vector loadable (broadcast LDS).
// ---------------------------------------------------------------------------
__global__ void __launch_bounds__(128, 3)
k_main(const float* __restrict__ x, const float* __restrict__ W0,
       const float* __restrict__ W1, float* __restrict__ out) {
  __shared__ alignas(16) float W0T[128 * 64];   // [k][j]
  __shared__ alignas(16) float W1T[64 * 64];    // [k][j]
  for (int i = threadIdx.x; i < 128 * 64; i += 128)
    W0T[i] = W0[(i & 63) * 128 + (i >> 6)];
  for (int i = threadIdx.x; i < 64 * 64; i += 128)
    W1T[i] = W1[(i & 63) * 64 + (i >> 6)];
  __syncthreads();

  for (int pt = blockIdx.x * 128 + threadIdx.x; pt < NPTS; pt += gridDim.x * 128) {
    float px = x[pt * 3 + 0], py = x[pt * 3 + 1], pz = x[pt * 3 + 2];
    unsigned long long h0[32];
#pragma unroll
    for (int i = 0; i < 32; i++) h0[i] = 0ull;

#pragma unroll 2
    for (int g = 0; g < NG; g++) {
      float4 m0 = __ldg(&g_xf[g * 3 + 0]);
      float4 m1 = __ldg(&g_xf[g * 3 + 1]);
      float4 m2 = __ldg(&g_xf[g * 3 + 2]);
      float gx = fmaf(m0.x, px, fmaf(m0.y, py, fmaf(m0.z, pz, m0.w)));
      float gy = fmaf(m1.x, px, fmaf(m1.y, py, fmaf(m1.z, pz, m1.w)));
      float gz = fmaf(m2.x, px, fmaf(m2.y, py, fmaf(m2.z, pz, m2.w)));
      float xf0 = floorf(gx), yf0 = floorf(gy), zf0 = floorf(gz);
      int x0 = (int)xf0, y0 = (int)yf0, z0 = (int)zf0;
      float fx = gx - xf0, fy = gy - yf0, fz = gz - zf0;

      int lx  = min(max(x0, 0), 63);
      int ly  = min(max(y0, 0), 63);
      int lz0 = min(max(z0, 0), 63);
      int lz1 = min(max(z0 + 1, 0), 63);
      const uint4* fb = g_feat + ((size_t)g << 18);
      uint4 q0 = __ldg(fb + ((lz0 << 12) | (ly << 6) | lx));
      uint4 q1 = __ldg(fb + ((lz1 << 12) | (ly << 6) | lx));

      // axis weights with out-of-range validity folded in (matches reference)
      float wx1 = (x0 >= -1 && x0 < 63) ? fx : 0.f;
      float wx0 = (x0 >= 0 && x0 < 64) ? (1.f - fx) : 0.f;
      float wy1 = (y0 >= -1 && y0 < 63) ? fy : 0.f;
      float wy0 = (y0 >= 0 && y0 < 64) ? (1.f - fy) : 0.f;
      float wz1 = (z0 >= -1 && z0 < 63) ? fz : 0.f;
      float wz0 = (z0 >= 0 && z0 < 64) ? (1.f - fz) : 0.f;

      // lower-boundary (x0<0 / y0<0) slot fix-ups for the duplicated layout
      bool sx = x0 < 0, sy = y0 < 0;
      unsigned c00 = q0.x;
      unsigned c01 = sx ? q0.x : q0.y;
      unsigned c10 = sy ? q0.x : q0.z;
      unsigned c11 = sy ? c01 : (sx ? q0.z : q0.w);
      unsigned d00 = q1.x;
      unsigned d01 = sx ? q1.x : q1.y;
      unsigned d10 = sy ? q1.x : q1.z;
      unsigned d11 = sy ? d01 : (sx ? q1.z : q1.w);

      float wzy00 = wz0 * wy0, wzy01 = wz0 * wy1, wzy10 = wz1 * wy0, wzy11 = wz1 * wy1;

      unsigned long long accA = 0ull, accB = 0ull;
      {
        float2 v;
        __half2 hv;
        hv = *reinterpret_cast<__half2*>(&c00); v = __half22float2(hv);
        accA = ffma2(pack2(wzy00 * wx0, wzy00 * wx0), pack2(v.x, v.y), accA);
        hv = *reinterpret_cast<__half2*>(&c01); v = __half22float2(hv);
        accB = ffma2(pack2(wzy00 * wx1, wzy00 * wx1), pack2(v.x, v.y), accB);
        hv = *reinterpret_cast<__half2*>(&c10); v = __half22float2(hv);
        accA = ffma2(pack2(wzy01 * wx0, wzy01 * wx0), pack2(v.x, v.y), accA);
        hv = *reinterpret_cast<__half2*>(&c11); v = __half22float2(hv);
        accB = ffma2(pack2(wzy01 * wx1, wzy01 * wx1), pack2(v.x, v.y), accB);
        hv = *reinterpret_cast<__half2*>(&d00); v = __half22float2(hv);
        accA = ffma2(pack2(wzy10 * wx0, wzy10 * wx0), pack2(v.x, v.y), accA);
        hv = *reinterpret_cast<__half2*>(&d01); v = __half22float2(hv);
        accB = ffma2(pack2(wzy10 * wx1, wzy10 * wx1), pack2(v.x, v.y), accB);
        hv = *reinterpret_cast<__half2*>(&d10); v = __half22float2(hv);
        accA = ffma2(pack2(wzy11 * wx0, wzy11 * wx0), pack2(v.x, v.y), accA);
        hv = *reinterpret_cast<__half2*>(&d11); v = __half22float2(hv);
        accB = ffma2(pack2(wzy11 * wx1, wzy11 * wx1), pack2(v.x, v.y), accB);
      }
      float2 fa = unpack2(accA), fbv = unpack2(accB);
      float f0 = fa.x + fbv.x;   // channel 0 -> feature index 2g
      float f1 = fa.y + fbv.y;   // channel 1 -> feature index 2g+1
      unsigned long long f0b = pack2(f0, f0);
      unsigned long long f1b = pack2(f1, f1);

      const ulonglong2* wr = reinterpret_cast<const ulonglong2*>(W0T + (g << 7));
#pragma unroll
      for (int j = 0; j < 16; j++) {
        ulonglong2 a = wr[j];        // W0 row k=2g, outputs 4j..4j+3
        ulonglong2 b = wr[16 + j];   // W0 row k=2g+1
        unsigned long long t0 = ffma2(f0b, a.x, h0[2 * j]);
        unsigned long long t1 = ffma2(f0b, a.y, h0[2 * j + 1]);
        h0[2 * j]     = ffma2(f1b, b.x, t0);
        h0[2 * j + 1] = ffma2(f1b, b.y, t1);
      }
    }

    // Layer 2: h1 = relu(W1 @ relu(h0))
    unsigned long long h1[32];
#pragma unroll
    for (int i = 0; i < 32; i++) h1[i] = 0ull;
#pragma unroll
    for (int p = 0; p < 32; p++) {
      float2 hp = unpack2(h0[p]);
      float a0 = fmaxf(hp.x, 0.f);
      float a1 = fmaxf(hp.y, 0.f);
      unsigned long long b0 = pack2(a0, a0);
      unsigned long long b1 = pack2(a1, a1);
      const ulonglong2* wr = reinterpret_cast<const ulonglong2*>(W1T + (p << 7));
#pragma unroll
      for (int j = 0; j < 16; j++) {
        ulonglong2 a = wr[j];        // W1 row k=2p
        ulonglong2 b = wr[16 + j];   // W1 row k=2p+1
        unsigned long long t0 = ffma2(b0, a.x, h1[2 * j]);
        unsigned long long t1 = ffma2(b0, a.y, h1[2 * j + 1]);
        h1[2 * j]     = ffma2(b1, b.x, t0);
        h1[2 * j + 1] = ffma2(b1, b.y, t1);
      }
    }

    // Output: W2 . relu(h1)
    float res = 0.f;
#pragma unroll
    for (int p = 0; p < 32; p++) {
      float2 hp = unpack2(h1[p]);
      float2 w = __ldg(&g_w2[p]);
      res = fmaf(fmaxf(hp.x, 0.f), w.x, res);
      res = fmaf(fmaxf(hp.y, 0.f), w.y, res);
    }
    out[pt] = res;
  }
}

extern "C" void kernel_launch(void* const* d_in, const int* in_sizes, int n_in,
                              void* d_out, int out_size) {
  const float* x  = (const float*)d_in[0];
  const float* r  = (const float*)d_in[1];
  const float* s  = (const float*)d_in[2];
  const float* t  = (const float*)d_in[3];
  const float* fe = (const float*)d_in[4];
  const float* W0 = (const float*)d_in[5];
  const float* W1 = (const float*)d_in[6];
  const float* W2 = (const float*)d_in[7];
  float* out = (float*)d_out;
  (void)in_sizes; (void)n_in; (void)out_size;

  k_prep<<<1, 64>>>(r, s, t, W2);
  k_repack<<<NG * 64, 256>>>(fe);
  k_main<<<456, 128>>>(x, W0, W1, out);
}

// round 3
// speedup vs baseline: 1.4860x; 1.4860x over previous
#include <cuda_runtime.h>
#include <cuda_fp16.h>

#define NPTS (1 << 19)
#define NG 64
#define NVOX (64 * 64 * 64)

// ---------------- static device scratch (allocation-free) ----------------
__device__ float4 g_xf[NG * 3];            // fused (rot*scale*31.5 | bias) rows
__device__ float2 g_w2[32];                // W2 as float2 pairs
__device__ uint4  g_feat[NG * NVOX];       // 256 MB: per-voxel 2x2 corner-dup fp16 (2ch)
__device__ unsigned g_F[NPTS * 64];        // 128 MB: features [pt][128] fp16 (as half2 words)
__device__ uint2  g_W0frag[8 * 8 * 32];    // mma B-fragments, layer0: [kt][nt][lane]
__device__ uint2  g_W1frag[4 * 8 * 32];    // mma B-fragments, layer1

static __device__ __forceinline__ unsigned long long ffma2(
    unsigned long long a, unsigned long long b, unsigned long long c) {
  unsigned long long d;
  asm("fma.rn.f32x2 %0, %1, %2, %3;" : "=l"(d) : "l"(a), "l"(b), "l"(c));
  return d;
}
static __device__ __forceinline__ unsigned long long pack2(float a, float b) {
  unsigned long long r;
  asm("mov.b64 %0, {%1, %2};" : "=l"(r) : "f"(a), "f"(b));
  return r;
}
static __device__ __forceinline__ float2 unpack2(unsigned long long v) {
  float2 r;
  asm("mov.b64 {%0, %1}, %2;" : "=f"(r.x), "=f"(r.y) : "l"(v));
  return r;
}
static __device__ __forceinline__ unsigned pack_h2(float a, float b) {
  __half2 h = __floats2half2_rn(a, b);
  return *reinterpret_cast<unsigned*>(&h);
}
static __device__ __forceinline__ void mma16816(float* d, const unsigned* a, uint2 b) {
  asm volatile(
      "mma.sync.aligned.m16n8k16.row.col.f32.f16.f16.f32 "
      "{%0,%1,%2,%3}, {%4,%5,%6,%7}, {%8,%9}, {%0,%1,%2,%3};"
      : "+f"(d[0]), "+f"(d[1]), "+f"(d[2]), "+f"(d[3])
      : "r"(a[0]), "r"(a[1]), "r"(a[2]), "r"(a[3]), "r"(b.x), "r"(b.y));
}

// ---------------------------------------------------------------------------
// Kernel 0: per-grid affine fold + W2 stage + pre-swizzle W0/W1 into
// m16n8k16 B-fragment order:  b0 = {Wt[kt*16+pr*2][n], Wt[..+1][n]},
// b1 = {Wt[kt*16+pr*2+8][n], Wt[..+9][n]},  n = nt*8 + lane/4, pr = lane%4,
// where Wt[k][n] = W[n][k].
// ---------------------------------------------------------------------------
__global__ void k_prep(const float* __restrict__ r, const float* __restrict__ s,
                       const float* __restrict__ t, const float* __restrict__ w2,
                       const float* __restrict__ W0, const float* __restrict__ W1) {
  int tid = threadIdx.x;
  if (tid < NG) {
    int g = tid;
    float qw = r[g * 4 + 0], qx = r[g * 4 + 1], qy = r[g * 4 + 2], qz = r[g * 4 + 3];
    float inv = 1.0f / sqrtf(qw * qw + qx * qx + qy * qy + qz * qz);
    qw *= inv; qx *= inv; qy *= inv; qz *= inv;
    float R[9];
    R[0] = 1.f - 2.f * (qy * qy + qz * qz); R[1] = 2.f * (qx * qy - qw * qz); R[2] = 2.f * (qx * qz + qw * qy);
    R[3] = 2.f * (qx * qy + qw * qz); R[4] = 1.f - 2.f * (qx * qx + qz * qz); R[5] = 2.f * (qy * qz - qw * qx);
    R[6] = 2.f * (qx * qz - qw * qy); R[7] = 2.f * (qy * qz + qw * qx); R[8] = 1.f - 2.f * (qx * qx + qy * qy);
#pragma unroll
    for (int i = 0; i < 3; i++) {
      float si = 31.5f * s[g * 3 + i];
      g_xf[g * 3 + i] = make_float4(si * R[i * 3 + 0], si * R[i * 3 + 1], si * R[i * 3 + 2],
                                    31.5f * t[g * 3 + i] + 31.5f);
    }
    reinterpret_cast<float*>(g_w2)[g] = w2[g];
  }
  // W0 fragments: 8 ktiles x 8 ntiles x 32 lanes
  for (int i = tid; i < 8 * 8 * 32; i += blockDim.x) {
    int kt = i >> 8, nt = (i >> 5) & 7, lane = i & 31;
    int grp = lane >> 2, pr = lane & 3;
    int n = nt * 8 + grp;
    int k0 = kt * 16 + pr * 2;
    uint2 b;
    b.x = pack_h2(W0[n * 128 + k0], W0[n * 128 + k0 + 1]);
    b.y = pack_h2(W0[n * 128 + k0 + 8], W0[n * 128 + k0 + 9]);
    g_W0frag[i] = b;
  }
  // W1 fragments: 4 ktiles x 8 ntiles x 32 lanes
  for (int i = tid; i < 4 * 8 * 32; i += blockDim.x) {
    int kt = i >> 8, nt = (i >> 5) & 7, lane = i & 31;
    int grp = lane >> 2, pr = lane & 3;
    int n = nt * 8 + grp;
    int k0 = kt * 16 + pr * 2;
    uint2 b;
    b.x = pack_h2(W1[n * 64 + k0], W1[n * 64 + k0 + 1]);
    b.y = pack_h2(W1[n * 64 + k0 + 8], W1[n * 64 + k0 + 9]);
    g_W1frag[i] = b;
  }
}

// ---------------------------------------------------------------------------
// Kernel 1: repack features [G,2,64,64,64] fp32 -> corner-duplicated fp16.
// Entry (g,z,y,x) = uint4 of 4 half2 covering the (y,x) 2x2 corner block.
// One block per (g,z) slice; slice staged in shared so global reads happen once.
// ---------------------------------------------------------------------------
__global__ void k_repack(const float* __restrict__ feat) {
  __shared__ float s0[4096];
  __shared__ float s1[4096];
  int b = blockIdx.x;            // b = g*64 + z
  int g = b >> 6;
  const float* p0 = feat + (((size_t)(2 * g)) << 18) + (((size_t)(b & 63)) << 12);
  const float* p1 = feat + (((size_t)(2 * g + 1)) << 18) + (((size_t)(b & 63)) << 12);
  for (int i = threadIdx.x; i < 4096; i += 256) { s0[i] = p0[i]; s1[i] = p1[i]; }
  __syncthreads();
  uint4* op = g_feat + (((size_t)b) << 12);
  for (int i = threadIdx.x; i < 4096; i += 256) {
    int y = i >> 6, xx = i & 63;
    int x1 = min(xx + 1, 63), y1 = min(y + 1, 63);
    uint4 e;
    e.x = pack_h2(s0[(y << 6) | xx], s1[(y << 6) | xx]);
    e.y = pack_h2(s0[(y << 6) | x1], s1[(y << 6) | x1]);
    e.z = pack_h2(s0[(y1 << 6) | xx], s1[(y1 << 6) | xx]);
    e.w = pack_h2(s0[(y1 << 6) | x1], s1[(y1 << 6) | x1]);
    op[i] = e;
  }
}

// ---------------------------------------------------------------------------
// Kernel 2: gather-only. One thread per point; accumulates 64 half2 features
// in registers, then writes the 256B feature row with 16 STG.128.
// ---------------------------------------------------------------------------
__global__ void __launch_bounds__(256)
k_feat(const float* __restrict__ x) {
  int pt = blockIdx.x * 256 + threadIdx.x;
  float px = x[pt * 3 + 0], py = x[pt * 3 + 1], pz = x[pt * 3 + 2];
  unsigned feats[64];

#pragma unroll 2
  for (int g = 0; g < NG; g++) {
    float4 m0 = __ldg(&g_xf[g * 3 + 0]);
    float4 m1 = __ldg(&g_xf[g * 3 + 1]);
    float4 m2 = __ldg(&g_xf[g * 3 + 2]);
    float gx = fmaf(m0.x, px, fmaf(m0.y, py, fmaf(m0.z, pz, m0.w)));
    float gy = fmaf(m1.x, px, fmaf(m1.y, py, fmaf(m1.z, pz, m1.w)));
    float gz = fmaf(m2.x, px, fmaf(m2.y, py, fmaf(m2.z, pz, m2.w)));
    float xf0 = floorf(gx), yf0 = floorf(gy), zf0 = floorf(gz);
    int x0 = (int)xf0, y0 = (int)yf0, z0 = (int)zf0;
    float fx = gx - xf0, fy = gy - yf0, fz = gz - zf0;

    int lx  = min(max(x0, 0), 63);
    int ly  = min(max(y0, 0), 63);
    int lz0 = min(max(z0, 0), 63);
    int lz1 = min(max(z0 + 1, 0), 63);
    const uint4* fb = g_feat + ((size_t)g << 18);
    uint4 q0 = __ldg(fb + ((lz0 << 12) | (ly << 6) | lx));
    uint4 q1 = __ldg(fb + ((lz1 << 12) | (ly << 6) | lx));

    float wx1 = (x0 >= -1 && x0 < 63) ? fx : 0.f;
    float wx0 = (x0 >= 0 && x0 < 64) ? (1.f - fx) : 0.f;
    float wy1 = (y0 >= -1 && y0 < 63) ? fy : 0.f;
    float wy0 = (y0 >= 0 && y0 < 64) ? (1.f - fy) : 0.f;
    float wz1 = (z0 >= -1 && z0 < 63) ? fz : 0.f;
    float wz0 = (z0 >= 0 && z0 < 64) ? (1.f - fz) : 0.f;

    bool sx = x0 < 0, sy = y0 < 0;
    unsigned c00 = q0.x;
    unsigned c01 = sx ? q0.x : q0.y;
    unsigned c10 = sy ? q0.x : q0.z;
    unsigned c11 = sy ? c01 : (sx ? q0.z : q0.w);
    unsigned d00 = q1.x;
    unsigned d01 = sx ? q1.x : q1.y;
    unsigned d10 = sy ? q1.x : q1.z;
    unsigned d11 = sy ? d01 : (sx ? q1.z : q1.w);

    float wzy00 = wz0 * wy0, wzy01 = wz0 * wy1, wzy10 = wz1 * wy0, wzy11 = wz1 * wy1;

    unsigned long long accA = 0ull, accB = 0ull;
    {
      float2 v;
      __half2 hv;
      hv = *reinterpret_cast<__half2*>(&c00); v = __half22float2(hv);
      accA = ffma2(pack2(wzy00 * wx0, wzy00 * wx0), pack2(v.x, v.y), accA);
      hv = *reinterpret_cast<__half2*>(&c01); v = __half22float2(hv);
      accB = ffma2(pack2(wzy00 * wx1, wzy00 * wx1), pack2(v.x, v.y), accB);
      hv = *reinterpret_cast<__half2*>(&c10); v = __half22float2(hv);
      accA = ffma2(pack2(wzy01 * wx0, wzy01 * wx0), pack2(v.x, v.y), accA);
      hv = *reinterpret_cast<__half2*>(&c11); v = __half22float2(hv);
      accB = ffma2(pack2(wzy01 * wx1, wzy01 * wx1), pack2(v.x, v.y), accB);
      hv = *reinterpret_cast<__half2*>(&d00); v = __half22float2(hv);
      accA = ffma2(pack2(wzy10 * wx0, wzy10 * wx0), pack2(v.x, v.y), accA);
      hv = *reinterpret_cast<__half2*>(&d01); v = __half22float2(hv);
      accB = ffma2(pack2(wzy10 * wx1, wzy10 * wx1), pack2(v.x, v.y), accB);
      hv = *reinterpret_cast<__half2*>(&d10); v = __half22float2(hv);
      accA = ffma2(pack2(wzy11 * wx0, wzy11 * wx0), pack2(v.x, v.y), accA);
      hv = *reinterpret_cast<__half2*>(&d11); v = __half22float2(hv);
      accB = ffma2(pack2(wzy11 * wx1, wzy11 * wx1), pack2(v.x, v.y), accB);
    }
    float2 fa = unpack2(accA), fbv = unpack2(accB);
    feats[g] = pack_h2(fa.x + fbv.x, fa.y + fbv.y);  // low = feat 2g, high = 2g+1
  }

  uint4* dst = reinterpret_cast<uint4*>(&g_F[pt * 64]);
#pragma unroll 4
  for (int j = 0; j < 16; j++) {
    dst[j] = make_uint4(feats[4 * j], feats[4 * j + 1], feats[4 * j + 2], feats[4 * j + 3]);
  }
}

// ---------------------------------------------------------------------------
// Kernel 3: MLP via HMMA m16n8k16. 128 points / CTA, 4 warps; warp w owns
// rows 32w..32w+31 (2 m-tiles). Layer0 D-fragments are re-packed in registers
// as layer1 A-fragments (identical thread layouts). Output reduced via shfl.
// ---------------------------------------------------------------------------
__global__ void __launch_bounds__(128)
k_mlp(float* __restrict__ out) {
  __shared__ unsigned Fs[128 * 68];   // rows padded to 68 words (136 halves)
  int t = threadIdx.x;
  int pt0 = blockIdx.x * 128;
  const uint4* src = reinterpret_cast<const uint4*>(&g_F[pt0 * 64]);
#pragma unroll
  for (int j = 0; j < 16; j++) {
    int i = t + 128 * j;
    int row = i >> 4, w = i & 15;
    *reinterpret_cast<uint4*>(&Fs[row * 68 + w * 4]) = __ldg(&src[i]);
  }
  __syncthreads();

  int lane = t & 31, warp = t >> 5;
  int grp = lane >> 2, pr = lane & 3;
  int rb = warp * 32;

  float acc[2][8][4];
#pragma unroll
  for (int mt = 0; mt < 2; mt++)
#pragma unroll
    for (int nt = 0; nt < 8; nt++)
#pragma unroll
      for (int q = 0; q < 4; q++) acc[mt][nt][q] = 0.f;

  // ---- layer 0: H0(128x64) = F(128x128) @ W0^T ----
#pragma unroll
  for (int kt = 0; kt < 8; kt++) {
    unsigned a[2][4];
#pragma unroll
    for (int mt = 0; mt < 2; mt++) {
      const unsigned* r0 = &Fs[(rb + mt * 16 + grp) * 68 + kt * 8 + pr];
      const unsigned* r1 = r0 + 8 * 68;
      a[mt][0] = r0[0]; a[mt][1] = r1[0]; a[mt][2] = r0[4]; a[mt][3] = r1[4];
    }
#pragma unroll
    for (int nt = 0; nt < 8; nt++) {
      uint2 b = __ldg(&g_W0frag[(kt * 8 + nt) * 32 + lane]);
      mma16816(acc[0][nt], a[0], b);
      mma16816(acc[1][nt], a[1], b);
    }
  }

  // ---- layer 1: H1(128x64) = relu(H0) @ W1^T ----
  float acc1[2][8][4];
#pragma unroll
  for (int mt = 0; mt < 2; mt++)
#pragma unroll
    for (int nt = 0; nt < 8; nt++)
#pragma unroll
      for (int q = 0; q < 4; q++) acc1[mt][nt][q] = 0.f;

#pragma unroll
  for (int kt = 0; kt < 4; kt++) {
    unsigned a[2][4];
#pragma unroll
    for (int mt = 0; mt < 2; mt++) {
      a[mt][0] = pack_h2(fmaxf(acc[mt][2 * kt][0], 0.f), fmaxf(acc[mt][2 * kt][1], 0.f));
      a[mt][1] = pack_h2(fmaxf(acc[mt][2 * kt][2], 0.f), fmaxf(acc[mt][2 * kt][3], 0.f));
      a[mt][2] = pack_h2(fmaxf(acc[mt][2 * kt + 1][0], 0.f), fmaxf(acc[mt][2 * kt + 1][1], 0.f));
      a[mt][3] = pack_h2(fmaxf(acc[mt][2 * kt + 1][2], 0.f), fmaxf(acc[mt][2 * kt + 1][3], 0.f));
    }
#pragma unroll
    for (int nt = 0; nt < 8; nt++) {
      uint2 b = __ldg(&g_W1frag[(kt * 8 + nt) * 32 + lane]);
      mma16816(acc1[0][nt], a[0], b);
      mma16816(acc1[1][nt], a[1], b);
    }
  }

  // ---- output: out = relu(H1) . w2 ----
#pragma unroll
  for (int mt = 0; mt < 2; mt++) {
    float p0 = 0.f, p1 = 0.f;
#pragma unroll
    for (int nt = 0; nt < 8; nt++) {
      float2 w = __ldg(&g_w2[nt * 4 + pr]);
      p0 = fmaf(fmaxf(acc1[mt][nt][0], 0.f), w.x, p0);
      p0 = fmaf(fmaxf(acc1[mt][nt][1], 0.f), w.y, p0);
      p1 = fmaf(fmaxf(acc1[mt][nt][2], 0.f), w.x, p1);
      p1 = fmaf(fmaxf(acc1[mt][nt][3], 0.f), w.y, p1);
    }
    p0 += __shfl_xor_sync(0xffffffffu, p0, 1);
    p0 += __shfl_xor_sync(0xffffffffu, p0, 2);
    p1 += __shfl_xor_sync(0xffffffffu, p1, 1);
    p1 += __shfl_xor_sync(0xffffffffu, p1, 2);
    if (pr == 0) {
      out[pt0 + rb + mt * 16 + grp] = p0;
      out[pt0 + rb + mt * 16 + grp + 8] = p1;
    }
  }
}

extern "C" void kernel_launch(void* const* d_in, const int* in_sizes, int n_in,
                              void* d_out, int out_size) {
  const float* x  = (const float*)d_in[0];
  const float* r  = (const float*)d_in[1];
  const float* s  = (const float*)d_in[2];
  const float* t  = (const float*)d_in[3];
  const float* fe = (const float*)d_in[4];
  const float* W0 = (const float*)d_in[5];
  const float* W1 = (const float*)d_in[6];
  const float* W2 = (const float*)d_in[7];
  float* out = (float*)d_out;
  (void)in_sizes; (void)n_in; (void)out_size;

  k_prep<<<1, 256>>>(r, s, t, W2, W0, W1);
  k_repack<<<NG * 64, 256>>>(fe);
  k_feat<<<NPTS / 256, 256>>>(x);
  k_mlp<<<NPTS / 128, 128>>>(out);
}

// round 4
// speedup vs baseline: 1.7503x; 1.1779x over previous
#include <cuda_runtime.h>
#include <cuda_fp16.h>

#define NPTS (1 << 19)
#define NG 64
#define NVOX (64 * 64 * 64)
#define NBINS 32768   // 15-bit Morton cells (32^3)

// ---------------- static device scratch (allocation-free) ----------------
__device__ float4 g_xf[NG * 3];            // fused (rot*scale*31.5 | bias) rows
__device__ float2 g_w2[32];                // W2 as float2 pairs
__device__ uint4  g_feat[NG * NVOX];       // 256 MB: per-voxel 2x2 corner-dup fp16 (2ch)
__device__ unsigned g_F[NPTS * 64];        // 128 MB: features [slot][128] fp16 (half2 words)
__device__ uint2  g_W0frag[8 * 8 * 32];    // mma B-fragments, layer0: [kt][nt][lane]
__device__ uint2  g_W1frag[4 * 8 * 32];    // mma B-fragments, layer1
__device__ int    g_hist[NBINS];           // Morton-cell histogram
__device__ int    g_binoff[NBINS];         // running bin offsets (rebuilt every launch)
__device__ float4 g_xs[NPTS];              // sorted points: (x,y,z, bitcast(orig idx))

static __device__ __forceinline__ unsigned long long ffma2(
    unsigned long long a, unsigned long long b, unsigned long long c) {
  unsigned long long d;
  asm("fma.rn.f32x2 %0, %1, %2, %3;" : "=l"(d) : "l"(a), "l"(b), "l"(c));
  return d;
}
static __device__ __forceinline__ unsigned long long pack2(float a, float b) {
  unsigned long long r;
  asm("mov.b64 %0, {%1, %2};" : "=l"(r) : "f"(a), "f"(b));
  return r;
}
static __device__ __forceinline__ float2 unpack2(unsigned long long v) {
  float2 r;
  asm("mov.b64 {%0, %1}, %2;" : "=f"(r.x), "=f"(r.y) : "l"(v));
  return r;
}
static __device__ __forceinline__ unsigned pack_h2(float a, float b) {
  __half2 h = __floats2half2_rn(a, b);
  return *reinterpret_cast<unsigned*>(&h);
}
static __device__ __forceinline__ void mma16816(float* d, const unsigned* a, uint2 b) {
  asm volatile(
      "mma.sync.aligned.m16n8k16.row.col.f32.f16.f16.f32 "
      "{%0,%1,%2,%3}, {%4,%5,%6,%7}, {%8,%9}, {%0,%1,%2,%3};"
      : "+f"(d[0]), "+f"(d[1]), "+f"(d[2]), "+f"(d[3])
      : "r"(a[0]), "r"(a[1]), "r"(a[2]), "r"(a[3]), "r"(b.x), "r"(b.y));
}
static __device__ __forceinline__ int part1by2_5(int v) {
  v &= 0x1f;
  v = (v | (v << 8)) & 0x100F;
  v = (v | (v << 4)) & 0x10C3;
  v = (v | (v << 2)) & 0x1249;
  return v;
}
static __device__ __forceinline__ int morton_cell(float px, float py, float pz) {
  int ix = min(31, max(0, (int)((px + 1.0f) * 16.0f)));
  int iy = min(31, max(0, (int)((py + 1.0f) * 16.0f)));
  int iz = min(31, max(0, (int)((pz + 1.0f) * 16.0f)));
  return part1by2_5(ix) | (part1by2_5(iy) << 1) | (part1by2_5(iz) << 2);
}

// ---------------------------------------------------------------------------
// Kernel 0: affine fold + W2 stage + W0/W1 mma-fragment swizzle + hist zero.
// ---------------------------------------------------------------------------
__global__ void k_prep(const float* __restrict__ r, const float* __restrict__ s,
                       const float* __restrict__ t, const float* __restrict__ w2,
                       const float* __restrict__ W0, const float* __restrict__ W1) {
  int tid = threadIdx.x;
  if (tid < NG) {
    int g = tid;
    float qw = r[g * 4 + 0], qx = r[g * 4 + 1], qy = r[g * 4 + 2], qz = r[g * 4 + 3];
    float inv = 1.0f / sqrtf(qw * qw + qx * qx + qy * qy + qz * qz);
    qw *= inv; qx *= inv; qy *= inv; qz *= inv;
    float R[9];
    R[0] = 1.f - 2.f * (qy * qy + qz * qz); R[1] = 2.f * (qx * qy - qw * qz); R[2] = 2.f * (qx * qz + qw * qy);
    R[3] = 2.f * (qx * qy + qw * qz); R[4] = 1.f - 2.f * (qx * qx + qz * qz); R[5] = 2.f * (qy * qz - qw * qx);
    R[6] = 2.f * (qx * qz - qw * qy); R[7] = 2.f * (qy * qz + qw * qx); R[8] = 1.f - 2.f * (qx * qx + qy * qy);
#pragma unroll
    for (int i = 0; i < 3; i++) {
      float si = 31.5f * s[g * 3 + i];
      g_xf[g * 3 + i] = make_float4(si * R[i * 3 + 0], si * R[i * 3 + 1], si * R[i * 3 + 2],
                                    31.5f * t[g * 3 + i] + 31.5f);
    }
    reinterpret_cast<float*>(g_w2)[g] = w2[g];
  }
  for (int i = tid; i < NBINS; i += blockDim.x) g_hist[i] = 0;
  // W0 fragments: 8 ktiles x 8 ntiles x 32 lanes
  for (int i = tid; i < 8 * 8 * 32; i += blockDim.x) {
    int kt = i >> 8, nt = (i >> 5) & 7, lane = i & 31;
    int grp = lane >> 2, pr = lane & 3;
    int n = nt * 8 + grp;
    int k0 = kt * 16 + pr * 2;
    uint2 b;
    b.x = pack_h2(W0[n * 128 + k0], W0[n * 128 + k0 + 1]);
    b.y = pack_h2(W0[n * 128 + k0 + 8], W0[n * 128 + k0 + 9]);
    g_W0frag[i] = b;
  }
  // W1 fragments: 4 ktiles x 8 ntiles x 32 lanes
  for (int i = tid; i < 4 * 8 * 32; i += blockDim.x) {
    int kt = i >> 8, nt = (i >> 5) & 7, lane = i & 31;
    int grp = lane >> 2, pr = lane & 3;
    int n = nt * 8 + grp;
    int k0 = kt * 16 + pr * 2;
    uint2 b;
    b.x = pack_h2(W1[n * 64 + k0], W1[n * 64 + k0 + 1]);
    b.y = pack_h2(W1[n * 64 + k0 + 8], W1[n * 64 + k0 + 9]);
    g_W1frag[i] = b;
  }
}

// ---------------------------------------------------------------------------
// Sort pass 1: histogram of Morton cells.
// ---------------------------------------------------------------------------
__global__ void k_hist(const float* __restrict__ x) {
  int pt = blockIdx.x * 256 + threadIdx.x;
  int c = morton_cell(x[pt * 3 + 0], x[pt * 3 + 1], x[pt * 3 + 2]);
  atomicAdd(&g_hist[c], 1);
}

// ---------------------------------------------------------------------------
// Sort pass 2: exclusive prefix sum over 32K bins (single block, 1024 thr).
// ---------------------------------------------------------------------------
__global__ void k_scan() {
  __shared__ int wsum[32];
  int t = threadIdx.x;
  int base = t * (NBINS / 1024);      // 32 bins per thread
  int loc[32];
  int s = 0;
#pragma unroll
  for (int i = 0; i < 32; i++) { loc[i] = s; s += g_hist[base + i]; }
  int lane = t & 31, wid = t >> 5;
  int v = s;
#pragma unroll
  for (int d = 1; d < 32; d <<= 1) {
    int n = __shfl_up_sync(0xffffffffu, v, d);
    if (lane >= d) v += n;
  }
  if (lane == 31) wsum[wid] = v;
  __syncthreads();
  if (wid == 0) {
    int w = wsum[lane];
#pragma unroll
    for (int d = 1; d < 32; d <<= 1) {
      int n = __shfl_up_sync(0xffffffffu, w, d);
      if (lane >= d) w += n;
    }
    wsum[lane] = w;
  }
  __syncthreads();
  int exc = (v - s) + (wid > 0 ? wsum[wid - 1] : 0);
#pragma unroll
  for (int i = 0; i < 32; i++) g_binoff[base + i] = exc + loc[i];
}

// ---------------------------------------------------------------------------
// Sort pass 3: scatter points into Morton order, carrying original index.
// ---------------------------------------------------------------------------
__global__ void k_scatter(const float* __restrict__ x) {
  int pt = blockIdx.x * 256 + threadIdx.x;
  float px = x[pt * 3 + 0], py = x[pt * 3 + 1], pz = x[pt * 3 + 2];
  int c = morton_cell(px, py, pz);
  int slot = atomicAdd(&g_binoff[c], 1);
  g_xs[slot] = make_float4(px, py, pz, __int_as_float(pt));
}

// ---------------------------------------------------------------------------
// Kernel 1: repack features [G,2,64,64,64] fp32 -> corner-duplicated fp16.
// ---------------------------------------------------------------------------
__global__ void k_repack(const float* __restrict__ feat) {
  __shared__ float s0[4096];
  __shared__ float s1[4096];
  int b = blockIdx.x;            // b = g*64 + z
  int g = b >> 6;
  const float* p0 = feat + (((size_t)(2 * g)) << 18) + (((size_t)(b & 63)) << 12);
  const float* p1 = feat + (((size_t)(2 * g + 1)) << 18) + (((size_t)(b & 63)) << 12);
  for (int i = threadIdx.x; i < 4096; i += 256) { s0[i] = p0[i]; s1[i] = p1[i]; }
  __syncthreads();
  uint4* op = g_feat + (((size_t)b) << 12);
  for (int i = threadIdx.x; i < 4096; i += 256) {
    int y = i >> 6, xx = i & 63;
    int x1 = min(xx + 1, 63), y1 = min(y + 1, 63);
    uint4 e;
    e.x = pack_h2(s0[(y << 6) | xx], s1[(y << 6) | xx]);
    e.y = pack_h2(s0[(y << 6) | x1], s1[(y << 6) | x1]);
    e.z = pack_h2(s0[(y1 << 6) | xx], s1[(y1 << 6) | xx]);
    e.w = pack_h2(s0[(y1 << 6) | x1], s1[(y1 << 6) | x1]);
    op[i] = e;
  }
}

// ---------------------------------------------------------------------------
// Kernel 2: gather (Morton-sorted). One thread per sorted slot; features
// computed in 16-grid chunks to keep register pressure low.
// ---------------------------------------------------------------------------
__global__ void __launch_bounds__(256)
k_feat() {
  int slot = blockIdx.x * 256 + threadIdx.x;
  float4 p = g_xs[slot];
  float px = p.x, py = p.y, pz = p.z;
  uint4* dst = reinterpret_cast<uint4*>(&g_F[slot * 64]);

  for (int gb = 0; gb < 4; gb++) {
    unsigned feats[16];
#pragma unroll 2
    for (int gi = 0; gi < 16; gi++) {
      int g = gb * 16 + gi;
      float4 m0 = __ldg(&g_xf[g * 3 + 0]);
      float4 m1 = __ldg(&g_xf[g * 3 + 1]);
      float4 m2 = __ldg(&g_xf[g * 3 + 2]);
      float gx = fmaf(m0.x, px, fmaf(m0.y, py, fmaf(m0.z, pz, m0.w)));
      float gy = fmaf(m1.x, px, fmaf(m1.y, py, fmaf(m1.z, pz, m1.w)));
      float gz = fmaf(m2.x, px, fmaf(m2.y, py, fmaf(m2.z, pz, m2.w)));
      float xf0 = floorf(gx), yf0 = floorf(gy), zf0 = floorf(gz);
      int x0 = (int)xf0, y0 = (int)yf0, z0 = (int)zf0;
      float fx = gx - xf0, fy = gy - yf0, fz = gz - zf0;

      int lx  = min(max(x0, 0), 63);
      int ly  = min(max(y0, 0), 63);
      int lz0 = min(max(z0, 0), 63);
      int lz1 = min(max(z0 + 1, 0), 63);
      const uint4* fb = g_feat + ((size_t)g << 18);
      uint4 q0 = __ldg(fb + ((lz0 << 12) | (ly << 6) | lx));
      uint4 q1 = __ldg(fb + ((lz1 << 12) | (ly << 6) | lx));

      float wx1 = (x0 >= -1 && x0 < 63) ? fx : 0.f;
      float wx0 = (x0 >= 0 && x0 < 64) ? (1.f - fx) : 0.f;
      float wy1 = (y0 >= -1 && y0 < 63) ? fy : 0.f;
      float wy0 = (y0 >= 0 && y0 < 64) ? (1.f - fy) : 0.f;
      float wz1 = (z0 >= -1 && z0 < 63) ? fz : 0.f;
      float wz0 = (z0 >= 0 && z0 < 64) ? (1.f - fz) : 0.f;

      bool sx = x0 < 0, sy = y0 < 0;
      unsigned c00 = q0.x;
      unsigned c01 = sx ? q0.x : q0.y;
      unsigned c10 = sy ? q0.x : q0.z;
      unsigned c11 = sy ? c01 : (sx ? q0.z : q0.w);
      unsigned d00 = q1.x;
      unsigned d01 = sx ? q1.x : q1.y;
      unsigned d10 = sy ? q1.x : q1.z;
      unsigned d11 = sy ? d01 : (sx ? q1.z : q1.w);

      float wzy00 = wz0 * wy0, wzy01 = wz0 * wy1, wzy10 = wz1 * wy0, wzy11 = wz1 * wy1;

      unsigned long long accA = 0ull, accB = 0ull;
      {
        float2 v;
        __half2 hv;
        hv = *reinterpret_cast<__half2*>(&c00); v = __half22float2(hv);
        accA = ffma2(pack2(wzy00 * wx0, wzy00 * wx0), pack2(v.x, v.y), accA);
        hv = *reinterpret_cast<__half2*>(&c01); v = __half22float2(hv);
        accB = ffma2(pack2(wzy00 * wx1, wzy00 * wx1), pack2(v.x, v.y), accB);
        hv = *reinterpret_cast<__half2*>(&c10); v = __half22float2(hv);
        accA = ffma2(pack2(wzy01 * wx0, wzy01 * wx0), pack2(v.x, v.y), accA);
        hv = *reinterpret_cast<__half2*>(&c11); v = __half22float2(hv);
        accB = ffma2(pack2(wzy01 * wx1, wzy01 * wx1), pack2(v.x, v.y), accB);
        hv = *reinterpret_cast<__half2*>(&d00); v = __half22float2(hv);
        accA = ffma2(pack2(wzy10 * wx0, wzy10 * wx0), pack2(v.x, v.y), accA);
        hv = *reinterpret_cast<__half2*>(&d01); v = __half22float2(hv);
        accB = ffma2(pack2(wzy10 * wx1, wzy10 * wx1), pack2(v.x, v.y), accB);
        hv = *reinterpret_cast<__half2*>(&d10); v = __half22float2(hv);
        accA = ffma2(pack2(wzy11 * wx0, wzy11 * wx0), pack2(v.x, v.y), accA);
        hv = *reinterpret_cast<__half2*>(&d11); v = __half22float2(hv);
        accB = ffma2(pack2(wzy11 * wx1, wzy11 * wx1), pack2(v.x, v.y), accB);
      }
      float2 fa = unpack2(accA), fbv = unpack2(accB);
      feats[gi] = pack_h2(fa.x + fbv.x, fa.y + fbv.y);
    }
#pragma unroll
    for (int j = 0; j < 4; j++) {
      dst[gb * 4 + j] = make_uint4(feats[4 * j], feats[4 * j + 1],
                                   feats[4 * j + 2], feats[4 * j + 3]);
    }
  }
}

// ---------------------------------------------------------------------------
// Kernel 3: MLP via HMMA m16n8k16 over sorted rows; outputs scattered back
// to original point order via the index carried in g_xs.w.
// ---------------------------------------------------------------------------
__global__ void __launch_bounds__(128)
k_mlp(float* __restrict__ out) {
  __shared__ unsigned Fs[128 * 68];   // rows padded to 68 words (136 halves)
  int t = threadIdx.x;
  int pt0 = blockIdx.x * 128;
  const uint4* src = reinterpret_cast<const uint4*>(&g_F[pt0 * 64]);
#pragma unroll
  for (int j = 0; j < 16; j++) {
    int i = t + 128 * j;
    int row = i >> 4, w = i & 15;
    *reinterpret_cast<uint4*>(&Fs[row * 68 + w * 4]) = __ldg(&src[i]);
  }
  __syncthreads();

  int lane = t & 31, warp = t >> 5;
  int grp = lane >> 2, pr = lane & 3;
  int rb = warp * 32;

  float acc[2][8][4];
#pragma unroll
  for (int mt = 0; mt < 2; mt++)
#pragma unroll
    for (int nt = 0; nt < 8; nt++)
#pragma unroll
      for (int q = 0; q < 4; q++) acc[mt][nt][q] = 0.f;

  // ---- layer 0 ----
#pragma unroll
  for (int kt = 0; kt < 8; kt++) {
    unsigned a[2][4];
#pragma unroll
    for (int mt = 0; mt < 2; mt++) {
      const unsigned* r0 = &Fs[(rb + mt * 16 + grp) * 68 + kt * 8 + pr];
      const unsigned* r1 = r0 + 8 * 68;
      a[mt][0] = r0[0]; a[mt][1] = r1[0]; a[mt][2] = r0[4]; a[mt][3] = r1[4];
    }
#pragma unroll
    for (int nt = 0; nt < 8; nt++) {
      uint2 b = __ldg(&g_W0frag[(kt * 8 + nt) * 32 + lane]);
      mma16816(acc[0][nt], a[0], b);
      mma16816(acc[1][nt], a[1], b);
    }
  }

  // ---- layer 1 ----
  float acc1[2][8][4];
#pragma unroll
  for (int mt = 0; mt < 2; mt++)
#pragma unroll
    for (int nt = 0; nt < 8; nt++)
#pragma unroll
      for (int q = 0; q < 4; q++) acc1[mt][nt][q] = 0.f;

#pragma unroll
  for (int kt = 0; kt < 4; kt++) {
    unsigned a[2][4];
#pragma unroll
    for (int mt = 0; mt < 2; mt++) {
      a[mt][0] = pack_h2(fmaxf(acc[mt][2 * kt][0], 0.f), fmaxf(acc[mt][2 * kt][1], 0.f));
      a[mt][1] = pack_h2(fmaxf(acc[mt][2 * kt][2], 0.f), fmaxf(acc[mt][2 * kt][3], 0.f));
      a[mt][2] = pack_h2(fmaxf(acc[mt][2 * kt + 1][0], 0.f), fmaxf(acc[mt][2 * kt + 1][1], 0.f));
      a[mt][3] = pack_h2(fmaxf(acc[mt][2 * kt + 1][2], 0.f), fmaxf(acc[mt][2 * kt + 1][3], 0.f));
    }
#pragma unroll
    for (int nt = 0; nt < 8; nt++) {
      uint2 b = __ldg(&g_W1frag[(kt * 8 + nt) * 32 + lane]);
      mma16816(acc1[0][nt], a[0], b);
      mma16816(acc1[1][nt], a[1], b);
    }
  }

  // ---- output: scatter back to original order ----
#pragma unroll
  for (int mt = 0; mt < 2; mt++) {
    float p0 = 0.f, p1 = 0.f;
#pragma unroll
    for (int nt = 0; nt < 8; nt++) {
      float2 w = __ldg(&g_w2[nt * 4 + pr]);
      p0 = fmaf(fmaxf(acc1[mt][nt][0], 0.f), w.x, p0);
      p0 = fmaf(fmaxf(acc1[mt][nt][1], 0.f), w.y, p0);
      p1 = fmaf(fmaxf(acc1[mt][nt][2], 0.f), w.x, p1);
      p1 = fmaf(fmaxf(acc1[mt][nt][3], 0.f), w.y, p1);
    }
    p0 += __shfl_xor_sync(0xffffffffu, p0, 1);
    p0 += __shfl_xor_sync(0xffffffffu, p0, 2);
    p1 += __shfl_xor_sync(0xffffffffu, p1, 1);
    p1 += __shfl_xor_sync(0xffffffffu, p1, 2);
    if (pr == 0) {
      int row0 = pt0 + rb + mt * 16 + grp;
      int i0 = __float_as_int(g_xs[row0].w);
      int i1 = __float_as_int(g_xs[row0 + 8].w);
      out[i0] = p0;
      out[i1] = p1;
    }
  }
}

extern "C" void kernel_launch(void* const* d_in, const int* in_sizes, int n_in,
                              void* d_out, int out_size) {
  const float* x  = (const float*)d_in[0];
  const float* r  = (const float*)d_in[1];
  const float* s  = (const float*)d_in[2];
  const float* t  = (const float*)d_in[3];
  const float* fe = (const float*)d_in[4];
  const float* W0 = (const float*)d_in[5];
  const float* W1 = (const float*)d_in[6];
  const float* W2 = (const float*)d_in[7];
  float* out = (float*)d_out;
  (void)in_sizes; (void)n_in; (void)out_size;

  k_prep<<<1, 256>>>(r, s, t, W2, W0, W1);
  k_hist<<<NPTS / 256, 256>>>(x);
  k_scan<<<1, 1024>>>();
  k_scatter<<<NPTS / 256, 256>>>(x);
  k_repack<<<NG * 64, 256>>>(fe);
  k_feat<<<NPTS / 256, 256>>>();
  k_mlp<<<NPTS / 128, 128>>>(out);
}

// round 6
// speedup vs baseline: 1.8245x; 1.0424x over previous
#include <cuda_runtime.h>
#include <cuda_fp16.h>

#define NPTS (1 << 19)
#define NG 64
#define NVOX (64 * 64 * 64)
#define NBINS 32768   // 15-bit Morton cells (32^3)

// ---------------- static device scratch (allocation-free) ----------------
__device__ float4 g_xf[NG * 3];            // fused (rot*scale*31.5 | bias) rows
__device__ float2 g_w2[32];                // W2 as float2 pairs
__device__ uint4  g_feat[NG * NVOX];       // 256 MB: Morton-voxel corner-dup fp16 (2ch)
__device__ unsigned g_F[NPTS * 64];        // 128 MB: features [slot][128] fp16 (half2 words)
__device__ uint2  g_W0frag[8 * 8 * 32];    // mma B-fragments, layer0: [kt][nt][lane]
__device__ uint2  g_W1frag[4 * 8 * 32];    // mma B-fragments, layer1
__device__ int    g_hist[NBINS];           // Morton-cell histogram
__device__ int    g_binoff[NBINS];         // running bin offsets (rebuilt every launch)
__device__ float4 g_xs[NPTS];              // sorted points: (x,y,z, bitcast(orig idx))

static __device__ __forceinline__ unsigned long long ffma2(
    unsigned long long a, unsigned long long b, unsigned long long c) {
  unsigned long long d;
  asm("fma.rn.f32x2 %0, %1, %2, %3;" : "=l"(d) : "l"(a), "l"(b), "l"(c));
  return d;
}
static __device__ __forceinline__ unsigned long long pack2(float a, float b) {
  unsigned long long r;
  asm("mov.b64 %0, {%1, %2};" : "=l"(r) : "f"(a), "f"(b));
  return r;
}
static __device__ __forceinline__ float2 unpack2(unsigned long long v) {
  float2 r;
  asm("mov.b64 {%0, %1}, %2;" : "=f"(r.x), "=f"(r.y) : "l"(v));
  return r;
}
static __device__ __forceinline__ unsigned pack_h2(float a, float b) {
  __half2 h = __floats2half2_rn(a, b);
  return *reinterpret_cast<unsigned*>(&h);
}
static __device__ __forceinline__ void mma16816(float* d, const unsigned* a, uint2 b) {
  asm volatile(
      "mma.sync.aligned.m16n8k16.row.col.f32.f16.f16.f32 "
      "{%0,%1,%2,%3}, {%4,%5,%6,%7}, {%8,%9}, {%0,%1,%2,%3};"
      : "+f"(d[0]), "+f"(d[1]), "+f"(d[2]), "+f"(d[3])
      : "r"(a[0]), "r"(a[1]), "r"(a[2]), "r"(a[3]), "r"(b.x), "r"(b.y));
}
// spread 6 bits b5..b0 to positions 15,12,9,6,3,0
static __device__ __forceinline__ unsigned spread6(unsigned v) {
  v = (v | (v << 8)) & 0x0300F00Fu;
  v = (v | (v << 4)) & 0x030C30C3u;
  v = (v | (v << 2)) & 0x09249249u;
  return v;
}
static __device__ __forceinline__ int part1by2_5(int v) {
  v &= 0x1f;
  v = (v | (v << 8)) & 0x100F;
  v = (v | (v << 4)) & 0x10C3;
  v = (v | (v << 2)) & 0x1249;
  return v;
}
static __device__ __forceinline__ int morton_cell(float px, float py, float pz) {
  int ix = min(31, max(0, (int)((px + 1.0f) * 16.0f)));
  int iy = min(31, max(0, (int)((py + 1.0f) * 16.0f)));
  int iz = min(31, max(0, (int)((pz + 1.0f) * 16.0f)));
  return part1by2_5(ix) | (part1by2_5(iy) << 1) | (part1by2_5(iz) << 2);
}

// ---------------------------------------------------------------------------
// Kernel 0: affine fold + W2 stage + W0/W1 mma-fragment swizzle + hist zero.
// ---------------------------------------------------------------------------
__global__ void k_prep(const float* __restrict__ r, const float* __restrict__ s,
                       const float* __restrict__ t, const float* __restrict__ w2,
                       const float* __restrict__ W0, const float* __restrict__ W1) {
  int tid = threadIdx.x;
  if (tid < NG) {
    int g = tid;
    float qw = r[g * 4 + 0], qx = r[g * 4 + 1], qy = r[g * 4 + 2], qz = r[g * 4 + 3];
    float inv = 1.0f / sqrtf(qw * qw + qx * qx + qy * qy + qz * qz);
    qw *= inv; qx *= inv; qy *= inv; qz *= inv;
    float R[9];
    R[0] = 1.f - 2.f * (qy * qy + qz * qz); R[1] = 2.f * (qx * qy - qw * qz); R[2] = 2.f * (qx * qz + qw * qy);
    R[3] = 2.f * (qx * qy + qw * qz); R[4] = 1.f - 2.f * (qx * qx + qz * qz); R[5] = 2.f * (qy * qz - qw * qx);
    R[6] = 2.f * (qx * qz - qw * qy); R[7] = 2.f * (qy * qz + qw * qx); R[8] = 1.f - 2.f * (qx * qx + qy * qy);
#pragma unroll
    for (int i = 0; i < 3; i++) {
      float si = 31.5f * s[g * 3 + i];
      g_xf[g * 3 + i] = make_float4(si * R[i * 3 + 0], si * R[i * 3 + 1], si * R[i * 3 + 2],
                                    31.5f * t[g * 3 + i] + 31.5f);
    }
    reinterpret_cast<float*>(g_w2)[g] = w2[g];
  }
  for (int i = tid; i < NBINS; i += blockDim.x) g_hist[i] = 0;
  // W0 fragments: 8 ktiles x 8 ntiles x 32 lanes
  for (int i = tid; i < 8 * 8 * 32; i += blockDim.x) {
    int kt = i >> 8, nt = (i >> 5) & 7, lane = i & 31;
    int grp = lane >> 2, pr = lane & 3;
    int n = nt * 8 + grp;
    int k0 = kt * 16 + pr * 2;
    uint2 b;
    b.x = pack_h2(W0[n * 128 + k0], W0[n * 128 + k0 + 1]);
    b.y = pack_h2(W0[n * 128 + k0 + 8], W0[n * 128 + k0 + 9]);
    g_W0frag[i] = b;
  }
  // W1 fragments: 4 ktiles x 8 ntiles x 32 lanes
  for (int i = tid; i < 4 * 8 * 32; i += blockDim.x) {
    int kt = i >> 8, nt = (i >> 5) & 7, lane = i & 31;
    int grp = lane >> 2, pr = lane & 3;
    int n = nt * 8 + grp;
    int k0 = kt * 16 + pr * 2;
    uint2 b;
    b.x = pack_h2(W1[n * 64 + k0], W1[n * 64 + k0 + 1]);
    b.y = pack_h2(W1[n * 64 + k0 + 8], W1[n * 64 + k0 + 9]);
    g_W1frag[i] = b;
  }
}

// ---------------------------------------------------------------------------
// Sort pass 1: histogram of Morton cells.
// ---------------------------------------------------------------------------
__global__ void k_hist(const float* __restrict__ x) {
  int pt = blockIdx.x * 256 + threadIdx.x;
  int c = morton_cell(x[pt * 3 + 0], x[pt * 3 + 1], x[pt * 3 + 2]);
  atomicAdd(&g_hist[c], 1);
}

// ---------------------------------------------------------------------------
// Sort pass 2: exclusive prefix sum over 32K bins (single block, 1024 thr).
// ---------------------------------------------------------------------------
__global__ void k_scan() {
  __shared__ int wsum[32];
  int t = threadIdx.x;
  int base = t * (NBINS / 1024);      // 32 bins per thread
  int loc[32];
  int s = 0;
#pragma unroll
  for (int i = 0; i < 32; i++) { loc[i] = s; s += g_hist[base + i]; }
  int lane = t & 31, wid = t >> 5;
  int v = s;
#pragma unroll
  for (int d = 1; d < 32; d <<= 1) {
    int n = __shfl_up_sync(0xffffffffu, v, d);
    if (lane >= d) v += n;
  }
  if (lane == 31) wsum[wid] = v;
  __syncthreads();
  if (wid == 0) {
    int w = wsum[lane];
#pragma unroll
    for (int d = 1; d < 32; d <<= 1) {
      int n = __shfl_up_sync(0xffffffffu, w, d);
      if (lane >= d) w += n;
    }
    wsum[lane] = w;
  }
  __syncthreads();
  int exc = (v - s) + (wid > 0 ? wsum[wid - 1] : 0);
#pragma unroll
  for (int i = 0; i < 32; i++) g_binoff[base + i] = exc + loc[i];
}

// ---------------------------------------------------------------------------
// Sort pass 3: scatter points into Morton order, carrying original index.
// ---------------------------------------------------------------------------
__global__ void k_scatter(const float* __restrict__ x) {
  int pt = blockIdx.x * 256 + threadIdx.x;
  float px = x[pt * 3 + 0], py = x[pt * 3 + 1], pz = x[pt * 3 + 2];
  int c = morton_cell(px, py, pz);
  int slot = atomicAdd(&g_binoff[c], 1);
  g_xs[slot] = make_float4(px, py, pz, __int_as_float(pt));
}

// ---------------------------------------------------------------------------
// Kernel 1: repack features [G,2,64,64,64] fp32 -> corner-duplicated fp16 at
// MORTON voxel addresses: idx = spread6(x) | spread6(y)<<1 | spread6(z)<<2.
// One block per (g,z) slice; slice staged in shared.
// ---------------------------------------------------------------------------
__global__ void k_repack(const float* __restrict__ feat) {
  __shared__ float s0[4096];
  __shared__ float s1[4096];
  int b = blockIdx.x;            // b = g*64 + z
  int g = b >> 6;
  int z = b & 63;
  const float* p0 = feat + (((size_t)(2 * g)) << 18) + (((size_t)z) << 12);
  const float* p1 = feat + (((size_t)(2 * g + 1)) << 18) + (((size_t)z) << 12);
  for (int i = threadIdx.x; i < 4096; i += 256) { s0[i] = p0[i]; s1[i] = p1[i]; }
  __syncthreads();
  uint4* op = g_feat + (((size_t)g) << 18);
  unsigned mz = spread6((unsigned)z) << 2;
  for (int i = threadIdx.x; i < 4096; i += 256) {
    int y = i >> 6, xx = i & 63;
    int x1 = min(xx + 1, 63), y1 = min(y + 1, 63);
    uint4 e;
    e.x = pack_h2(s0[(y << 6) | xx], s1[(y << 6) | xx]);
    e.y = pack_h2(s0[(y << 6) | x1], s1[(y << 6) | x1]);
    e.z = pack_h2(s0[(y1 << 6) | xx], s1[(y1 << 6) | xx]);
    e.w = pack_h2(s0[(y1 << 6) | x1], s1[(y1 << 6) | x1]);
    op[spread6((unsigned)xx) | (spread6((unsigned)y) << 1) | mz] = e;
  }
}

// ---------------------------------------------------------------------------
// Kernel 2: gather (Morton-sorted points, Morton-laid voxels). One thread per
// sorted slot; features computed in 16-grid chunks.
// ---------------------------------------------------------------------------
__global__ void __launch_bounds__(256)
k_feat() {
  int slot = blockIdx.x * 256 + threadIdx.x;
  float4 p = g_xs[slot];
  float px = p.x, py = p.y, pz = p.z;
  uint4* dst = reinterpret_cast<uint4*>(&g_F[slot * 64]);

  for (int gb = 0; gb < 4; gb++) {
    unsigned feats[16];
#pragma unroll 4
    for (int gi = 0; gi < 16; gi++) {
      int g = gb * 16 + gi;
      float4 m0 = __ldg(&g_xf[g * 3 + 0]);
      float4 m1 = __ldg(&g_xf[g * 3 + 1]);
      float4 m2 = __ldg(&g_xf[g * 3 + 2]);
      float gx = fmaf(m0.x, px, fmaf(m0.y, py, fmaf(m0.z, pz, m0.w)));
      float gy = fmaf(m1.x, px, fmaf(m1.y, py, fmaf(m1.z, pz, m1.w)));
      float gz = fmaf(m2.x, px, fmaf(m2.y, py, fmaf(m2.z, pz, m2.w)));
      float xf0 = floorf(gx), yf0 = floorf(gy), zf0 = floorf(gz);
      int x0 = (int)xf0, y0 = (int)yf0, z0 = (int)zf0;
      float fx = gx - xf0, fy = gy - yf0, fz = gz - zf0;

      int lx  = min(max(x0, 0), 63);
      int ly  = min(max(y0, 0), 63);
      int lz0 = min(max(z0, 0), 63);
      int lz1 = min(max(z0 + 1, 0), 63);
      const uint4* fb = g_feat + ((size_t)g << 18);
      unsigned mxy = spread6((unsigned)lx) | (spread6((unsigned)ly) << 1);
      uint4 q0 = __ldg(fb + (mxy | (spread6((unsigned)lz0) << 2)));
      uint4 q1 = __ldg(fb + (mxy | (spread6((unsigned)lz1) << 2)));

      float wx1 = (x0 >= -1 && x0 < 63) ? fx : 0.f;
      float wx0 = (x0 >= 0 && x0 < 64) ? (1.f - fx) : 0.f;
      float wy1 = (y0 >= -1 && y0 < 63) ? fy : 0.f;
      float wy0 = (y0 >= 0 && y0 < 64) ? (1.f - fy) : 0.f;
      float wz1 = (z0 >= -1 && z0 < 63) ? fz : 0.f;
      float wz0 = (z0 >= 0 && z0 < 64) ? (1.f - fz) : 0.f;

      bool sx = x0 < 0, sy = y0 < 0;
      unsigned c00 = q0.x;
      unsigned c01 = sx ? q0.x : q0.y;
      unsigned c10 = sy ? q0.x : q0.z;
      unsigned c11 = sy ? c01 : (sx ? q0.z : q0.w);
      unsigned d00 = q1.x;
      unsigned d01 = sx ? q1.x : q1.y;
      unsigned d10 = sy ? q1.x : q1.z;
      unsigned d11 = sy ? d01 : (sx ? q1.z : q1.w);

      float wzy00 = wz0 * wy0, wzy01 = wz0 * wy1, wzy10 = wz1 * wy0, wzy11 = wz1 * wy1;

      unsigned long long accA = 0ull, accB = 0ull;
      {
        float2 v;
        __half2 hv;
        hv = *reinterpret_cast<__half2*>(&c00); v = __half22float2(hv);
        accA = ffma2(pack2(wzy00 * wx0, wzy00 * wx0), pack2(v.x, v.y), accA);
        hv = *reinterpret_cast<__half2*>(&c01); v = __half22float2(hv);
        accB = ffma2(pack2(wzy00 * wx1, wzy00 * wx1), pack2(v.x, v.y), accB);
        hv = *reinterpret_cast<__half2*>(&c10); v = __half22float2(hv);
        accA = ffma2(pack2(wzy01 * wx0, wzy01 * wx0), pack2(v.x, v.y), accA);
        hv = *reinterpret_cast<__half2*>(&c11); v = __half22float2(hv);
        accB = ffma2(pack2(wzy01 * wx1, wzy01 * wx1), pack2(v.x, v.y), accB);
        hv = *reinterpret_cast<__half2*>(&d00); v = __half22float2(hv);
        accA = ffma2(pack2(wzy10 * wx0, wzy10 * wx0), pack2(v.x, v.y), accA);
        hv = *reinterpret_cast<__half2*>(&d01); v = __half22float2(hv);
        accB = ffma2(pack2(wzy10 * wx1, wzy10 * wx1), pack2(v.x, v.y), accB);
        hv = *reinterpret_cast<__half2*>(&d10); v = __half22float2(hv);
        accA = ffma2(pack2(wzy11 * wx0, wzy11 * wx0), pack2(v.x, v.y), accA);
        hv = *reinterpret_cast<__half2*>(&d11); v = __half22float2(hv);
        accB = ffma2(pack2(wzy11 * wx1, wzy11 * wx1), pack2(v.x, v.y), accB);
      }
      float2 fa = unpack2(accA), fbv = unpack2(accB);
      feats[gi] = pack_h2(fa.x + fbv.x, fa.y + fbv.y);
    }
#pragma unroll
    for (int j = 0; j < 4; j++) {
      dst[gb * 4 + j] = make_uint4(feats[4 * j], feats[4 * j + 1],
                                   feats[4 * j + 2], feats[4 * j + 3]);
    }
  }
}

// ---------------------------------------------------------------------------
// Kernel 3: MLP via HMMA m16n8k16 over sorted rows; outputs scattered back
// to original point order via the index carried in g_xs.w.
// ---------------------------------------------------------------------------
__global__ void __launch_bounds__(128)
k_mlp(float* __restrict__ out) {
  __shared__ unsigned Fs[128 * 68];   // rows padded to 68 words (136 halves)
  int t = threadIdx.x;
  int pt0 = blockIdx.x * 128;
  const uint4* src = reinterpret_cast<const uint4*>(&g_F[pt0 * 64]);
#pragma unroll
  for (int j = 0; j < 16; j++) {
    int i = t + 128 * j;
    int row = i >> 4, w = i & 15;
    *reinterpret_cast<uint4*>(&Fs[row * 68 + w * 4]) = __ldg(&src[i]);
  }
  __syncthreads();

  int lane = t & 31, warp = t >> 5;
  int grp = lane >> 2, pr = lane & 3;
  int rb = warp * 32;

  float acc[2][8][4];
#pragma unroll
  for (int mt = 0; mt < 2; mt++)
#pragma unroll
    for (int nt = 0; nt < 8; nt++)
#pragma unroll
      for (int q = 0; q < 4; q++) acc[mt][nt][q] = 0.f;

  // ---- layer 0 ----
#pragma unroll
  for (int kt = 0; kt < 8; kt++) {
    unsigned a[2][4];
#pragma unroll
    for (int mt = 0; mt < 2; mt++) {
      const unsigned* r0 = &Fs[(rb + mt * 16 + grp) * 68 + kt * 8 + pr];
      const unsigned* r1 = r0 + 8 * 68;
      a[mt][0] = r0[0]; a[mt][1] = r1[0]; a[mt][2] = r0[4]; a[mt][3] = r1[4];
    }
#pragma unroll
    for (int nt = 0; nt < 8; nt++) {
      uint2 b = __ldg(&g_W0frag[(kt * 8 + nt) * 32 + lane]);
      mma16816(acc[0][nt], a[0], b);
      mma16816(acc[1][nt], a[1], b);
    }
  }

  // ---- layer 1 ----
  float acc1[2][8][4];
#pragma unroll
  for (int mt = 0; mt < 2; mt++)
#pragma unroll
    for (int nt = 0; nt < 8; nt++)
#pragma unroll
      for (int q = 0; q < 4; q++) acc1[mt][nt][q] = 0.f;

#pragma unroll
  for (int kt = 0; kt < 4; kt++) {
    unsigned a[2][4];
#pragma unroll
    for (int mt = 0; mt < 2; mt++) {
      a[mt][0] = pack_h2(fmaxf(acc[mt][2 * kt][0], 0.f), fmaxf(acc[mt][2 * kt][1], 0.f));
      a[mt][1] = pack_h2(fmaxf(acc[mt][2 * kt][2], 0.f), fmaxf(acc[mt][2 * kt][3], 0.f));
      a[mt][2] = pack_h2(fmaxf(acc[mt][2 * kt + 1][0], 0.f), fmaxf(acc[mt][2 * kt + 1][1], 0.f));
      a[mt][3] = pack_h2(fmaxf(acc[mt][2 * kt + 1][2], 0.f), fmaxf(acc[mt][2 * kt + 1][3], 0.f));
    }
#pragma unroll
    for (int nt = 0; nt < 8; nt++) {
      uint2 b = __ldg(&g_W1frag[(kt * 8 + nt) * 32 + lane]);
      mma16816(acc1[0][nt], a[0], b);
      mma16816(acc1[1][nt], a[1], b);
    }
  }

  // ---- output: scatter back to original order ----
#pragma unroll
  for (int mt = 0; mt < 2; mt++) {
    float p0 = 0.f, p1 = 0.f;
#pragma unroll
    for (int nt = 0; nt < 8; nt++) {
      float2 w = __ldg(&g_w2[nt * 4 + pr]);
      p0 = fmaf(fmaxf(acc1[mt][nt][0], 0.f), w.x, p0);
      p0 = fmaf(fmaxf(acc1[mt][nt][1], 0.f), w.y, p0);
      p1 = fmaf(fmaxf(acc1[mt][nt][2], 0.f), w.x, p1);
      p1 = fmaf(fmaxf(acc1[mt][nt][3], 0.f), w.y, p1);
    }
    p0 += __shfl_xor_sync(0xffffffffu, p0, 1);
    p0 += __shfl_xor_sync(0xffffffffu, p0, 2);
    p1 += __shfl_xor_sync(0xffffffffu, p1, 1);
    p1 += __shfl_xor_sync(0xffffffffu, p1, 2);
    if (pr == 0) {
      int row0 = pt0 + rb + mt * 16 + grp;
      int i0 = __float_as_int(g_xs[row0].w);
      int i1 = __float_as_int(g_xs[row0 + 8].w);
      out[i0] = p0;
      out[i1] = p1;
    }
  }
}

extern "C" void kernel_launch(void* const* d_in, const int* in_sizes, int n_in,
                              void* d_out, int out_size) {
  const float* x  = (const float*)d_in[0];
  const float* r  = (const float*)d_in[1];
  const float* s  = (const float*)d_in[2];
  const float* t  = (const float*)d_in[3];
  const float* fe = (const float*)d_in[4];
  const float* W0 = (const float*)d_in[5];
  const float* W1 = (const float*)d_in[6];
  const float* W2 = (const float*)d_in[7];
  float* out = (float*)d_out;
  (void)in_sizes; (void)n_in; (void)out_size;

  k_prep<<<1, 256>>>(r, s, t, W2, W0, W1);
  k_hist<<<NPTS / 256, 256>>>(x);
  k_scan<<<1, 1024>>>();
  k_scatter<<<NPTS / 256, 256>>>(x);
  k_repack<<<NG * 64, 256>>>(fe);
  k_feat<<<NPTS / 256, 256>>>();
  k_mlp<<<NPTS / 128, 128>>>(out);
}